// round 14
// baseline (speedup 1.0000x reference)
#include <cuda_runtime.h>
#include <cuda_fp16.h>
#include <cstdint>

#define Bb 4
#define Tt 2048
#define Cc 1024
#define NHh 16
#define Dd 64
#define Mtot (Bb * Tt)   // 8192

// ------------------------- scratch (__device__ globals) --------------------
__device__ __half g_qkv[(size_t)Bb * Tt * 3 * Cc];   // [B,T,3C] fp16
__device__ __half g_xh[(size_t)Mtot * Cc];
__device__ __half g_wh[(size_t)3 * Cc * Cc];
__device__ __half g_ph[(size_t)Cc * Cc];
__device__ __half g_ah[(size_t)Mtot * Cc];
// head-major [b*16+h][t][d] fp16 for attention
__device__ __half g_qh[(size_t)Mtot * Cc];
__device__ __half g_kh[(size_t)Mtot * Cc];
__device__ __half g_vh[(size_t)Mtot * Cc];

// ------------------------- helpers -----------------------------------------
__device__ __forceinline__ uint32_t smem_u32(const void* p) {
    uint32_t a;
    asm("{ .reg .u64 t; cvta.to.shared.u64 t, %1; cvt.u32.u64 %0, t; }"
        : "=r"(a) : "l"(p));
    return a;
}

__device__ __forceinline__ void ldmx4(uint32_t& r0, uint32_t& r1,
                                      uint32_t& r2, uint32_t& r3, uint32_t addr) {
    asm volatile("ldmatrix.sync.aligned.m8n8.x4.shared.b16 {%0,%1,%2,%3}, [%4];"
                 : "=r"(r0), "=r"(r1), "=r"(r2), "=r"(r3) : "r"(addr));
}

__device__ __forceinline__ void ldmx4t(uint32_t& r0, uint32_t& r1,
                                       uint32_t& r2, uint32_t& r3, uint32_t addr) {
    asm volatile("ldmatrix.sync.aligned.m8n8.x4.trans.shared.b16 {%0,%1,%2,%3}, [%4];"
                 : "=r"(r0), "=r"(r1), "=r"(r2), "=r"(r3) : "r"(addr));
}

__device__ __forceinline__ void mmaf16(float* d, const uint32_t* a,
                                       uint32_t b0, uint32_t b1) {
    asm volatile(
        "mma.sync.aligned.m16n8k16.row.col.f32.f16.f16.f32 "
        "{%0,%1,%2,%3}, {%4,%5,%6,%7}, {%8,%9}, {%0,%1,%2,%3};"
        : "+f"(d[0]), "+f"(d[1]), "+f"(d[2]), "+f"(d[3])
        : "r"(a[0]), "r"(a[1]), "r"(a[2]), "r"(a[3]), "r"(b0), "r"(b1));
}

__device__ __forceinline__ uint32_t packf16(float lo, float hi) {
    uint32_t r;
    asm("cvt.rn.f16x2.f32 %0, %1, %2;" : "=r"(r) : "f"(hi), "f"(lo));
    return r;
}

__device__ __forceinline__ float ex2(float x) {
    float r;
    asm("ex2.approx.ftz.f32 %0, %1;" : "=f"(r) : "f"(x));
    return r;
}

__device__ __forceinline__ void cp16(uint32_t dst, const void* src) {
    asm volatile("cp.async.cg.shared.global [%0], [%1], 16;" :: "r"(dst), "l"(src));
}
#define CP_COMMIT() asm volatile("cp.async.commit_group;" ::: "memory")
#define CP_WAIT0()  asm volatile("cp.async.wait_group 0;" ::: "memory")
#define CP_WAIT1()  asm volatile("cp.async.wait_group 1;" ::: "memory")

// ---------------------------------------------------------------------------
// fp16 single-pass GEMM via mma.sync, cp.async 2-stage, BK=64, 2 CTAs/SM.
// 256 threads, 8 warps (2m x 4n), warp tile 64x32, CTA tile 128x128.
// ---------------------------------------------------------------------------
#define SPAD 72
#define GMAT (128 * SPAD * 2u)

template <int OUTF16>
__global__ __launch_bounds__(256, 2)
void gemm_f16(const __half* __restrict__ A,
              const __half* __restrict__ B,
              const float* __restrict__ bias,
              void* __restrict__ CoutV, int N, int K)
{
    extern __shared__ char gsm[];
    const uint32_t sb = smem_u32(gsm);

    const int tid  = threadIdx.x;
    const int wid  = tid >> 5;
    const int lane = tid & 31;
    const int mw   = wid >> 2;
    const int nw   = wid & 3;
    const int m0   = blockIdx.y * 128;
    const int n0   = blockIdx.x * 128;

    auto stoff = [&](int s, int m) -> uint32_t {
        return sb + (uint32_t)(s * 2 + m) * GMAT;
    };

    const int kq = K >> 3;
    const int nk = K >> 6;
    const int rl = tid >> 3, cl = tid & 7;

    auto load_stage = [&](int s, int kc) {
#pragma unroll
        for (int i = 0; i < 4; i++) {
            const int r = rl + i * 32;
            const uint32_t so = (uint32_t)(r * (SPAD * 2) + cl * 16);
            cp16(stoff(s, 0) + so, (const uint4*)A + (size_t)(m0 + r) * kq + kc * 8 + cl);
            cp16(stoff(s, 1) + so, (const uint4*)B + (size_t)(n0 + r) * kq + kc * 8 + cl);
        }
    };

    const int lrow = lane & 15;
    const int lk   = (lane >> 4) * 8;
    uint32_t aoff[4], boff[2];
#pragma unroll
    for (int mt = 0; mt < 4; mt++)
        aoff[mt] = (uint32_t)(((mw * 64 + mt * 16 + lrow) * SPAD + lk) * 2);
#pragma unroll
    for (int ng = 0; ng < 2; ng++)
        boff[ng] = (uint32_t)(((nw * 32 + ng * 16 + lrow) * SPAD + lk) * 2);

    float acc[4][4][4];
#pragma unroll
    for (int i = 0; i < 4; i++)
#pragma unroll
        for (int j = 0; j < 4; j++)
#pragma unroll
            for (int e = 0; e < 4; e++) acc[i][j][e] = 0.f;

    load_stage(0, 0);
    CP_COMMIT();

    for (int kc = 0; kc < nk; kc++) {
        const int s = kc & 1;
        if (kc + 1 < nk) {
            load_stage(s ^ 1, kc + 1);
            CP_COMMIT();
            CP_WAIT1();
        } else {
            CP_WAIT0();
        }
        __syncthreads();

        const uint32_t uA = stoff(s, 0), uB = stoff(s, 1);
#pragma unroll
        for (int ks = 0; ks < 4; ks++) {
            const uint32_t kb = ks * 32;
            uint32_t ah[4][4];
#pragma unroll
            for (int mt = 0; mt < 4; mt++)
                ldmx4(ah[mt][0], ah[mt][1], ah[mt][2], ah[mt][3], uA + aoff[mt] + kb);
            uint32_t bh[2][4];
#pragma unroll
            for (int ng = 0; ng < 2; ng++)
                ldmx4(bh[ng][0], bh[ng][1], bh[ng][2], bh[ng][3], uB + boff[ng] + kb);
#pragma unroll
            for (int mt = 0; mt < 4; mt++)
#pragma unroll
                for (int ng = 0; ng < 2; ng++)
#pragma unroll
                    for (int sub = 0; sub < 2; sub++)
                        mmaf16(acc[mt][ng * 2 + sub], ah[mt],
                               bh[ng][sub], bh[ng][sub + 2]);
        }
        __syncthreads();
    }

    const int erow = lane >> 2;
    const int ecol = (lane & 3) * 2;
#pragma unroll
    for (int mt = 0; mt < 4; mt++) {
#pragma unroll
        for (int nt = 0; nt < 4; nt++) {
            const int row = m0 + mw * 64 + mt * 16 + erow;
            const int col = n0 + nw * 32 + nt * 8 + ecol;
            const float b0 = bias[col], b1 = bias[col + 1];
            if (OUTF16) {
                __half* C = (__half*)CoutV;
                *(__half2*)(C + (size_t)row * N + col) =
                    __floats2half2_rn(acc[mt][nt][0] + b0, acc[mt][nt][1] + b1);
                *(__half2*)(C + (size_t)(row + 8) * N + col) =
                    __floats2half2_rn(acc[mt][nt][2] + b0, acc[mt][nt][3] + b1);
            } else {
                float* C = (float*)CoutV;
                float2 v;
                v.x = acc[mt][nt][0] + b0;
                v.y = acc[mt][nt][1] + b1;
                *(float2*)(C + (size_t)row * N + col) = v;
                v.x = acc[mt][nt][2] + b0;
                v.y = acc[mt][nt][3] + b1;
                *(float2*)(C + (size_t)(row + 8) * N + col) = v;
            }
        }
    }
}
#define GEMM_SMEM (2u * 2u * GMAT)   // 73728

// ---------------------------------------------------------------------------
// Fused fp32 -> fp16 conversion of x, w_attn, w_proj in ONE launch.
// ---------------------------------------------------------------------------
#define N4_X ((Mtot * Cc) / 4)
#define N4_W ((3 * Cc * Cc) / 4)
#define N4_P ((Cc * Cc) / 4)

__global__ void cvt_all(const float4* __restrict__ x,
                        const float4* __restrict__ w,
                        const float4* __restrict__ p,
                        __half2* __restrict__ xo,
                        __half2* __restrict__ wo,
                        __half2* __restrict__ po)
{
    int i = blockIdx.x * 256 + threadIdx.x;
    const float4* src;
    __half2* dst;
    if (i < N4_X) {
        src = x + i; dst = xo + 2 * i;
    } else if (i < N4_X + N4_W) {
        int j = i - N4_X;
        src = w + j; dst = wo + 2 * j;
    } else if (i < N4_X + N4_W + N4_P) {
        int j = i - N4_X - N4_W;
        src = p + j; dst = po + 2 * j;
    } else return;
    float4 v = *src;
    dst[0] = __floats2half2_rn(v.x, v.y);
    dst[1] = __floats2half2_rn(v.z, v.w);
}

// ---------------------------------------------------------------------------
// Fused RoPE + head-major relayout (fp16 in/out).
// q pre-scaled by log2e/sqrt(D) so flash softmax works in exp2 domain.
// ---------------------------------------------------------------------------
__global__ void rope_f16(const float* __restrict__ cosp,
                         const float* __restrict__ sinp)
{
    int idx = blockIdx.x * 256 + threadIdx.x;
    int ds = idx & 7;
    int h  = (idx >> 3) & 15;
    int t  = (idx >> 7) & 2047;
    int b  = idx >> 18;
    int d0 = ds * 4;

    const __half* base = g_qkv + ((size_t)(b * Tt + t)) * (3 * Cc) + h * Dd;
    auto ld4 = [&](const __half* p, float* o) {
        __half2 u0 = *(const __half2*)p;
        __half2 u1 = *(const __half2*)(p + 2);
        float2 f0 = __half22float2(u0), f1 = __half22float2(u1);
        o[0] = f0.x; o[1] = f0.y; o[2] = f1.x; o[3] = f1.y;
    };
    float q1[4], q2[4], k1[4], k2[4];
    ld4(base + d0, q1);           ld4(base + d0 + 32, q2);
    ld4(base + Cc + d0, k1);      ld4(base + Cc + d0 + 32, k2);
    __half2 v1a = *(const __half2*)(base + 2 * Cc + d0);
    __half2 v1b = *(const __half2*)(base + 2 * Cc + d0 + 2);
    __half2 v2a = *(const __half2*)(base + 2 * Cc + d0 + 32);
    __half2 v2b = *(const __half2*)(base + 2 * Cc + d0 + 34);

    float4 cw = *(const float4*)(cosp + t * Dd + d0);
    float4 sw = *(const float4*)(sinp + t * Dd + d0);
    float cc[4] = {cw.x, cw.y, cw.z, cw.w};
    float ss[4] = {sw.x, sw.y, sw.z, sw.w};

    const float sc = 0.125f * 1.44269504f;
    size_t ob = (((size_t)(b * NHh + h)) * Tt + t) * Dd;
    __half2* qp = (__half2*)(g_qh + ob + d0);
    __half2* kp = (__half2*)(g_kh + ob + d0);
    __half2* vp = (__half2*)(g_vh + ob + d0);

    float qa[4], qb[4], ka[4], kb[4];
#pragma unroll
    for (int i = 0; i < 4; i++) {
        qa[i] = (q1[i] * cc[i] - q2[i] * ss[i]) * sc;
        qb[i] = (q2[i] * cc[i] + q1[i] * ss[i]) * sc;
        ka[i] = k1[i] * cc[i] - k2[i] * ss[i];
        kb[i] = k2[i] * cc[i] + k1[i] * ss[i];
    }
    qp[0]  = __floats2half2_rn(qa[0], qa[1]);
    qp[1]  = __floats2half2_rn(qa[2], qa[3]);
    qp[16] = __floats2half2_rn(qb[0], qb[1]);
    qp[17] = __floats2half2_rn(qb[2], qb[3]);
    kp[0]  = __floats2half2_rn(ka[0], ka[1]);
    kp[1]  = __floats2half2_rn(ka[2], ka[3]);
    kp[16] = __floats2half2_rn(kb[0], kb[1]);
    kp[17] = __floats2half2_rn(kb[2], kb[3]);
    vp[0]  = v1a; vp[1]  = v1b;
    vp[16] = v2a; vp[17] = v2b;
}

// ---------------------------------------------------------------------------
// Flash attention: 128 q rows/CTA, 256 threads (8 warps x 16 rows),
// 64-key tiles double-buffered, exp2 softmax, rescale-skip. 2 CTAs/SM.
// smem: 2 bufs x {K,V} (4 x 9216) + Q (2 x 9216) = 55296 B.
// ---------------------------------------------------------------------------
#define SROW 72
#define TILE_B 9216u
#define FLASH_SMEM (6u * TILE_B)

__global__ __launch_bounds__(256, 2) void flash_mma()
{
    extern __shared__ char fsm[];
    const uint32_t sb = smem_u32(fsm);

    const int bh = blockIdx.y;
    const int qt = (gridDim.x - 1) - blockIdx.x;   // heavy tiles first
    const int q0 = qt * 128;
    const int tid = threadIdx.x, wid = tid >> 5, lane = tid & 31;

    const size_t hb = (size_t)bh * Tt * Dd;
    const __half* Q = g_qh + hb + (size_t)q0 * Dd;
    const __half* Kp = g_kh + hb;
    const __half* Vp = g_vh + hb;

    auto soff = [&](int buf, int mat) -> uint32_t {
        return sb + (uint32_t)(buf * 2 + mat) * TILE_B;
    };
    const uint32_t soffQ = sb + 4 * TILE_B;   // 128 rows x 144 B

    // prologue: Q (128x64) + tile 0 (K,V 64x64)
    {
#pragma unroll
        for (int i = 0; i < 4; i++) {
            int lin = tid + i * 256;
            int r = lin >> 3, c = (lin & 7) * 8;
            uint32_t so = (uint32_t)(r * SROW + c) * 2;
            cp16(soffQ + so, Q + (size_t)r * Dd + c);
        }
        CP_COMMIT();
#pragma unroll
        for (int i = 0; i < 2; i++) {
            int lin = tid + i * 256;
            int r = lin >> 3, c = (lin & 7) * 8;
            uint32_t so = (uint32_t)(r * SROW + c) * 2;
            cp16(soff(0, 0) + so, Kp + (size_t)r * Dd + c);
            cp16(soff(0, 1) + so, Vp + (size_t)r * Dd + c);
        }
        CP_COMMIT();
        CP_WAIT0();
        __syncthreads();
    }

    uint32_t QF[4][4];
    {
        const int row = wid * 16 + (lane & 15);
        const int ck  = (lane >> 4) * 8;
#pragma unroll
        for (int kk = 0; kk < 4; kk++) {
            uint32_t ao = (uint32_t)(row * SROW + kk * 16 + ck) * 2;
            ldmx4(QF[kk][0], QF[kk][1], QF[kk][2], QF[kk][3], soffQ + ao);
        }
    }

    float O[8][4];
#pragma unroll
    for (int i = 0; i < 8; i++)
#pragma unroll
        for (int e = 0; e < 4; e++) O[i][e] = 0.f;
    float m0 = -1e30f, m1 = -1e30f, l0 = 0.f, l1 = 0.f;

    const int klrow = lane & 15;
    const int klk   = (lane >> 4) * 8;
    const int vg    = lane >> 3;
    const int vrow_in = (vg & 1) * 8 + (lane & 7);
    const int vcol_of = (vg >> 1) * 8;

    const int njt = 2 * qt + 2;
    for (int jt = 0; jt < njt; jt++) {
        const int buf = jt & 1;
        __syncthreads();
        if (jt + 1 < njt) {
            const int j1 = (jt + 1) * 64;
#pragma unroll
            for (int i = 0; i < 2; i++) {
                int lin = tid + i * 256;
                int r = lin >> 3, c = (lin & 7) * 8;
                uint32_t so = (uint32_t)(r * SROW + c) * 2;
                size_t gi = (size_t)(j1 + r) * Dd + c;
                cp16(soff(buf ^ 1, 0) + so, Kp + gi);
                cp16(soff(buf ^ 1, 1) + so, Vp + gi);
            }
            CP_COMMIT();
            CP_WAIT1();
        } else {
            CP_WAIT0();
        }
        __syncthreads();

        float S[8][4];
#pragma unroll
        for (int i = 0; i < 8; i++)
#pragma unroll
            for (int e = 0; e < 4; e++) S[i][e] = 0.f;

#pragma unroll
        for (int jg = 0; jg < 4; jg++) {
#pragma unroll
            for (int kk = 0; kk < 4; kk++) {
                uint32_t ao = (uint32_t)((jg * 16 + klrow) * SROW + kk * 16 + klk) * 2;
                uint32_t k0, k1, k2, k3;
                ldmx4(k0, k1, k2, k3, soff(buf, 0) + ao);
                mmaf16(S[jg * 2 + 0], QF[kk], k0, k2);
                mmaf16(S[jg * 2 + 1], QF[kk], k1, k3);
            }
        }

        // causal mask on the last two tiles (off = q0 - j0 in {64, 0} -> use
        // global compare: mask if col > row + off where off = q0 - jt*64)
        if (jt >= 2 * qt) {
            const int off = q0 - jt * 64;          // 0 or -64
            const int r0l = wid * 16 + (lane >> 2);
            const int cb  = (lane & 3) * 2;
#pragma unroll
            for (int nf = 0; nf < 8; nf++) {
                int c0 = nf * 8 + cb;
                if (c0     > r0l + off)     S[nf][0] = -1e30f;
                if (c0 + 1 > r0l + off)     S[nf][1] = -1e30f;
                if (c0     > r0l + 8 + off) S[nf][2] = -1e30f;
                if (c0 + 1 > r0l + 8 + off) S[nf][3] = -1e30f;
            }
        }

        float tm0 = -1e30f, tm1 = -1e30f;
#pragma unroll
        for (int nf = 0; nf < 8; nf++) {
            tm0 = fmaxf(tm0, fmaxf(S[nf][0], S[nf][1]));
            tm1 = fmaxf(tm1, fmaxf(S[nf][2], S[nf][3]));
        }
        tm0 = fmaxf(tm0, __shfl_xor_sync(0xffffffff, tm0, 1));
        tm0 = fmaxf(tm0, __shfl_xor_sync(0xffffffff, tm0, 2));
        tm1 = fmaxf(tm1, __shfl_xor_sync(0xffffffff, tm1, 1));
        tm1 = fmaxf(tm1, __shfl_xor_sync(0xffffffff, tm1, 2));

        const bool grew = (tm0 > m0) || (tm1 > m1);
        if (__any_sync(0xffffffff, grew)) {
            float m0n = fmaxf(m0, tm0), m1n = fmaxf(m1, tm1);
            float sc0 = ex2(m0 - m0n), sc1 = ex2(m1 - m1n);
            l0 *= sc0; l1 *= sc1;
#pragma unroll
            for (int i = 0; i < 8; i++) {
                O[i][0] *= sc0; O[i][1] *= sc0;
                O[i][2] *= sc1; O[i][3] *= sc1;
            }
            m0 = m0n; m1 = m1n;
        }
#pragma unroll
        for (int nf = 0; nf < 8; nf++) {
            S[nf][0] = ex2(S[nf][0] - m0);
            S[nf][1] = ex2(S[nf][1] - m0);
            S[nf][2] = ex2(S[nf][2] - m1);
            S[nf][3] = ex2(S[nf][3] - m1);
            l0 += S[nf][0] + S[nf][1];
            l1 += S[nf][2] + S[nf][3];
        }

#pragma unroll
        for (int kk = 0; kk < 4; kk++) {
            const float* s0 = S[2 * kk];
            const float* s1 = S[2 * kk + 1];
            uint32_t P[4];
            P[0] = packf16(s0[0], s0[1]);
            P[1] = packf16(s0[2], s0[3]);
            P[2] = packf16(s1[0], s1[1]);
            P[3] = packf16(s1[2], s1[3]);
#pragma unroll
            for (int dc = 0; dc < 4; dc++) {
                uint32_t vo = (uint32_t)((kk * 16 + vrow_in) * SROW + dc * 16 + vcol_of) * 2;
                uint32_t v0, v1, v2, v3;
                ldmx4t(v0, v1, v2, v3, soff(buf, 1) + vo);
                mmaf16(O[dc * 2 + 0], P, v0, v1);
                mmaf16(O[dc * 2 + 1], P, v2, v3);
            }
        }
    }

    l0 += __shfl_xor_sync(0xffffffff, l0, 1);
    l0 += __shfl_xor_sync(0xffffffff, l0, 2);
    l1 += __shfl_xor_sync(0xffffffff, l1, 1);
    l1 += __shfl_xor_sync(0xffffffff, l1, 2);
    const float i0 = 1.f / l0, i1 = 1.f / l1;

    const int b = bh >> 4, h = bh & 15;
    const int t0 = q0 + wid * 16 + (lane >> 2);
    const int t1 = t0 + 8;
    const size_t co = (size_t)h * Dd + (lane & 3) * 2;
    __half2* a0 = (__half2*)(g_ah + (size_t)(b * Tt + t0) * Cc + co);
    __half2* a1 = (__half2*)(g_ah + (size_t)(b * Tt + t1) * Cc + co);
#pragma unroll
    for (int nf = 0; nf < 8; nf++) {
        a0[nf * 4] = __floats2half2_rn(O[nf][0] * i0, O[nf][1] * i0);
        a1[nf * 4] = __floats2half2_rn(O[nf][2] * i1, O[nf][3] * i1);
    }
}

// ---------------------------------------------------------------------------
extern "C" void kernel_launch(void* const* d_in, const int* in_sizes, int n_in,
                              void* d_out, int out_size)
{
    const float* x      = (const float*)d_in[0];
    const float* w_attn = (const float*)d_in[1];
    const float* b_attn = (const float*)d_in[2];
    const float* w_proj = (const float*)d_in[3];
    const float* b_proj = (const float*)d_in[4];
    const float* cosp   = (const float*)d_in[5];
    const float* sinp   = (const float*)d_in[6];
    float* out = (float*)d_out;

    void *p_xh, *p_wh, *p_ph, *p_ah, *p_qkv;
    cudaGetSymbolAddress(&p_xh, g_xh);
    cudaGetSymbolAddress(&p_wh, g_wh);
    cudaGetSymbolAddress(&p_ph, g_ph);
    cudaGetSymbolAddress(&p_ah, g_ah);
    cudaGetSymbolAddress(&p_qkv, g_qkv);

    static bool once = false;
    if (!once) {
        cudaFuncSetAttribute(flash_mma,
                             cudaFuncAttributeMaxDynamicSharedMemorySize, FLASH_SMEM);
        cudaFuncSetAttribute(gemm_f16<0>,
                             cudaFuncAttributeMaxDynamicSharedMemorySize, GEMM_SMEM);
        cudaFuncSetAttribute(gemm_f16<1>,
                             cudaFuncAttributeMaxDynamicSharedMemorySize, GEMM_SMEM);
        cudaFuncSetAttribute(gemm_f16<0>,
                             cudaFuncAttributePreferredSharedMemoryCarveout, 100);
        cudaFuncSetAttribute(gemm_f16<1>,
                             cudaFuncAttributePreferredSharedMemoryCarveout, 100);
        once = true;
    }

    // 1) fused fp16 conversions (one launch)
    {
        int total = N4_X + N4_W + N4_P;   // 3,145,728
        cvt_all<<<(total + 255) / 256, 256>>>(
            (const float4*)x, (const float4*)w_attn, (const float4*)w_proj,
            (__half2*)p_xh, (__half2*)p_wh, (__half2*)p_ph);
    }

    // 2) QKV projection -> g_qkv fp16
    {
        dim3 grid((3 * Cc) / 128, Mtot / 128);
        gemm_f16<1><<<grid, 256, GEMM_SMEM>>>(
            (const __half*)p_xh, (const __half*)p_wh,
            b_attn, p_qkv, 3 * Cc, Cc);
    }

    // 3) fused RoPE + relayout (fp16 in/out)
    {
        int total = Bb * Tt * NHh * 8;
        rope_f16<<<total / 256, 256>>>(cosp, sinp);
    }

    // 4) flash attention (fp16, exp2 softmax, 128-row q tiles) -> g_ah fp16
    {
        dim3 grid(Tt / 128, Bb * NHh);
        flash_mma<<<grid, 256, FLASH_SMEM>>>();
    }

    // 5) output projection -> out fp32
    {
        dim3 grid(Cc / 128, Mtot / 128);
        gemm_f16<0><<<grid, 256, GEMM_SMEM>>>(
            (const __half*)p_ah, (const __half*)p_ph,
            b_proj, out, Cc, Cc);
    }
}

// round 16
// speedup vs baseline: 1.0030x; 1.0030x over previous
#include <cuda_runtime.h>
#include <cuda_fp16.h>
#include <cstdint>

#define Bb 4
#define Tt 2048
#define Cc 1024
#define NHh 16
#define Dd 64
#define Mtot (Bb * Tt)   // 8192

// ------------------------- scratch (__device__ globals) --------------------
__device__ __half g_qkv[(size_t)Bb * Tt * 3 * Cc];   // [B,T,3C] fp16
__device__ __half g_xh[(size_t)Mtot * Cc];
__device__ __half g_wh[(size_t)3 * Cc * Cc];
__device__ __half g_ph[(size_t)Cc * Cc];
__device__ __half g_ah[(size_t)Mtot * Cc];
// head-major [b*16+h][t][d] fp16 for attention
__device__ __half g_qh[(size_t)Mtot * Cc];
__device__ __half g_kh[(size_t)Mtot * Cc];
__device__ __half g_vh[(size_t)Mtot * Cc];

// ------------------------- helpers -----------------------------------------
__device__ __forceinline__ uint32_t smem_u32(const void* p) {
    uint32_t a;
    asm("{ .reg .u64 t; cvta.to.shared.u64 t, %1; cvt.u32.u64 %0, t; }"
        : "=r"(a) : "l"(p));
    return a;
}

__device__ __forceinline__ void ldmx4(uint32_t& r0, uint32_t& r1,
                                      uint32_t& r2, uint32_t& r3, uint32_t addr) {
    asm volatile("ldmatrix.sync.aligned.m8n8.x4.shared.b16 {%0,%1,%2,%3}, [%4];"
                 : "=r"(r0), "=r"(r1), "=r"(r2), "=r"(r3) : "r"(addr));
}

__device__ __forceinline__ void ldmx4t(uint32_t& r0, uint32_t& r1,
                                       uint32_t& r2, uint32_t& r3, uint32_t addr) {
    asm volatile("ldmatrix.sync.aligned.m8n8.x4.trans.shared.b16 {%0,%1,%2,%3}, [%4];"
                 : "=r"(r0), "=r"(r1), "=r"(r2), "=r"(r3) : "r"(addr));
}

__device__ __forceinline__ void mmaf16(float* d, const uint32_t* a,
                                       uint32_t b0, uint32_t b1) {
    asm volatile(
        "mma.sync.aligned.m16n8k16.row.col.f32.f16.f16.f32 "
        "{%0,%1,%2,%3}, {%4,%5,%6,%7}, {%8,%9}, {%0,%1,%2,%3};"
        : "+f"(d[0]), "+f"(d[1]), "+f"(d[2]), "+f"(d[3])
        : "r"(a[0]), "r"(a[1]), "r"(a[2]), "r"(a[3]), "r"(b0), "r"(b1));
}

__device__ __forceinline__ uint32_t packf16(float lo, float hi) {
    uint32_t r;
    asm("cvt.rn.f16x2.f32 %0, %1, %2;" : "=r"(r) : "f"(hi), "f"(lo));
    return r;
}

__device__ __forceinline__ float ex2(float x) {
    float r;
    asm("ex2.approx.ftz.f32 %0, %1;" : "=f"(r) : "f"(x));
    return r;
}

__device__ __forceinline__ void cp16(uint32_t dst, const void* src) {
    asm volatile("cp.async.cg.shared.global [%0], [%1], 16;" :: "r"(dst), "l"(src));
}
#define CP_COMMIT() asm volatile("cp.async.commit_group;" ::: "memory")
#define CP_WAIT0()  asm volatile("cp.async.wait_group 0;" ::: "memory")
#define CP_WAIT1()  asm volatile("cp.async.wait_group 1;" ::: "memory")

// ---------------------------------------------------------------------------
// fp16 single-pass GEMM via mma.sync, cp.async 2-stage, BK=64, 2 CTAs/SM.
// 256 threads, 8 warps (2m x 4n), warp tile 64x32, CTA tile 128x128.
// ---------------------------------------------------------------------------
#define SPAD 72
#define GMAT (128 * SPAD * 2u)

template <int OUTF16>
__global__ __launch_bounds__(256, 2)
void gemm_f16(const __half* __restrict__ A,
              const __half* __restrict__ B,
              const float* __restrict__ bias,
              void* __restrict__ CoutV, int N, int K)
{
    extern __shared__ char gsm[];
    const uint32_t sb = smem_u32(gsm);

    const int tid  = threadIdx.x;
    const int wid  = tid >> 5;
    const int lane = tid & 31;
    const int mw   = wid >> 2;
    const int nw   = wid & 3;
    const int m0   = blockIdx.y * 128;
    const int n0   = blockIdx.x * 128;

    auto stoff = [&](int s, int m) -> uint32_t {
        return sb + (uint32_t)(s * 2 + m) * GMAT;
    };

    const int kq = K >> 3;
    const int nk = K >> 6;
    const int rl = tid >> 3, cl = tid & 7;

    auto load_stage = [&](int s, int kc) {
#pragma unroll
        for (int i = 0; i < 4; i++) {
            const int r = rl + i * 32;
            const uint32_t so = (uint32_t)(r * (SPAD * 2) + cl * 16);
            cp16(stoff(s, 0) + so, (const uint4*)A + (size_t)(m0 + r) * kq + kc * 8 + cl);
            cp16(stoff(s, 1) + so, (const uint4*)B + (size_t)(n0 + r) * kq + kc * 8 + cl);
        }
    };

    const int lrow = lane & 15;
    const int lk   = (lane >> 4) * 8;
    uint32_t aoff[4], boff[2];
#pragma unroll
    for (int mt = 0; mt < 4; mt++)
        aoff[mt] = (uint32_t)(((mw * 64 + mt * 16 + lrow) * SPAD + lk) * 2);
#pragma unroll
    for (int ng = 0; ng < 2; ng++)
        boff[ng] = (uint32_t)(((nw * 32 + ng * 16 + lrow) * SPAD + lk) * 2);

    float acc[4][4][4];
#pragma unroll
    for (int i = 0; i < 4; i++)
#pragma unroll
        for (int j = 0; j < 4; j++)
#pragma unroll
            for (int e = 0; e < 4; e++) acc[i][j][e] = 0.f;

    load_stage(0, 0);
    CP_COMMIT();

    for (int kc = 0; kc < nk; kc++) {
        const int s = kc & 1;
        if (kc + 1 < nk) {
            load_stage(s ^ 1, kc + 1);
            CP_COMMIT();
            CP_WAIT1();
        } else {
            CP_WAIT0();
        }
        __syncthreads();

        const uint32_t uA = stoff(s, 0), uB = stoff(s, 1);
#pragma unroll
        for (int ks = 0; ks < 4; ks++) {
            const uint32_t kb = ks * 32;
            uint32_t ah[4][4];
#pragma unroll
            for (int mt = 0; mt < 4; mt++)
                ldmx4(ah[mt][0], ah[mt][1], ah[mt][2], ah[mt][3], uA + aoff[mt] + kb);
            uint32_t bh[2][4];
#pragma unroll
            for (int ng = 0; ng < 2; ng++)
                ldmx4(bh[ng][0], bh[ng][1], bh[ng][2], bh[ng][3], uB + boff[ng] + kb);
#pragma unroll
            for (int mt = 0; mt < 4; mt++)
#pragma unroll
                for (int ng = 0; ng < 2; ng++)
#pragma unroll
                    for (int sub = 0; sub < 2; sub++)
                        mmaf16(acc[mt][ng * 2 + sub], ah[mt],
                               bh[ng][sub], bh[ng][sub + 2]);
        }
        __syncthreads();
    }

    const int erow = lane >> 2;
    const int ecol = (lane & 3) * 2;
#pragma unroll
    for (int mt = 0; mt < 4; mt++) {
#pragma unroll
        for (int nt = 0; nt < 4; nt++) {
            const int row = m0 + mw * 64 + mt * 16 + erow;
            const int col = n0 + nw * 32 + nt * 8 + ecol;
            const float b0 = bias[col], b1 = bias[col + 1];
            if (OUTF16) {
                __half* C = (__half*)CoutV;
                *(__half2*)(C + (size_t)row * N + col) =
                    __floats2half2_rn(acc[mt][nt][0] + b0, acc[mt][nt][1] + b1);
                *(__half2*)(C + (size_t)(row + 8) * N + col) =
                    __floats2half2_rn(acc[mt][nt][2] + b0, acc[mt][nt][3] + b1);
            } else {
                float* C = (float*)CoutV;
                float2 v;
                v.x = acc[mt][nt][0] + b0;
                v.y = acc[mt][nt][1] + b1;
                *(float2*)(C + (size_t)row * N + col) = v;
                v.x = acc[mt][nt][2] + b0;
                v.y = acc[mt][nt][3] + b1;
                *(float2*)(C + (size_t)(row + 8) * N + col) = v;
            }
        }
    }
}
#define GEMM_SMEM (2u * 2u * GMAT)   // 73728

// ---------------------------------------------------------------------------
// Fused fp32 -> fp16 conversion of x, w_attn, w_proj in ONE launch.
// ---------------------------------------------------------------------------
#define N4_X ((Mtot * Cc) / 4)
#define N4_W ((3 * Cc * Cc) / 4)
#define N4_P ((Cc * Cc) / 4)

__global__ void cvt_all(const float4* __restrict__ x,
                        const float4* __restrict__ w,
                        const float4* __restrict__ p,
                        __half2* __restrict__ xo,
                        __half2* __restrict__ wo,
                        __half2* __restrict__ po)
{
    int i = blockIdx.x * 256 + threadIdx.x;
    const float4* src;
    __half2* dst;
    if (i < N4_X) {
        src = x + i; dst = xo + 2 * i;
    } else if (i < N4_X + N4_W) {
        int j = i - N4_X;
        src = w + j; dst = wo + 2 * j;
    } else if (i < N4_X + N4_W + N4_P) {
        int j = i - N4_X - N4_W;
        src = p + j; dst = po + 2 * j;
    } else return;
    float4 v = *src;
    dst[0] = __floats2half2_rn(v.x, v.y);
    dst[1] = __floats2half2_rn(v.z, v.w);
}

// ---------------------------------------------------------------------------
// Fused RoPE + head-major relayout (fp16 in/out).
// q pre-scaled by log2e/sqrt(D) so flash softmax works in exp2 domain.
// ---------------------------------------------------------------------------
__global__ void rope_f16(const float* __restrict__ cosp,
                         const float* __restrict__ sinp)
{
    int idx = blockIdx.x * 256 + threadIdx.x;
    int ds = idx & 7;
    int h  = (idx >> 3) & 15;
    int t  = (idx >> 7) & 2047;
    int b  = idx >> 18;
    int d0 = ds * 4;

    const __half* base = g_qkv + ((size_t)(b * Tt + t)) * (3 * Cc) + h * Dd;
    auto ld4 = [&](const __half* p, float* o) {
        __half2 u0 = *(const __half2*)p;
        __half2 u1 = *(const __half2*)(p + 2);
        float2 f0 = __half22float2(u0), f1 = __half22float2(u1);
        o[0] = f0.x; o[1] = f0.y; o[2] = f1.x; o[3] = f1.y;
    };
    float q1[4], q2[4], k1[4], k2[4];
    ld4(base + d0, q1);           ld4(base + d0 + 32, q2);
    ld4(base + Cc + d0, k1);      ld4(base + Cc + d0 + 32, k2);
    __half2 v1a = *(const __half2*)(base + 2 * Cc + d0);
    __half2 v1b = *(const __half2*)(base + 2 * Cc + d0 + 2);
    __half2 v2a = *(const __half2*)(base + 2 * Cc + d0 + 32);
    __half2 v2b = *(const __half2*)(base + 2 * Cc + d0 + 34);

    float4 cw = *(const float4*)(cosp + t * Dd + d0);
    float4 sw = *(const float4*)(sinp + t * Dd + d0);
    float cc[4] = {cw.x, cw.y, cw.z, cw.w};
    float ss[4] = {sw.x, sw.y, sw.z, sw.w};

    const float sc = 0.125f * 1.44269504f;
    size_t ob = (((size_t)(b * NHh + h)) * Tt + t) * Dd;
    __half2* qp = (__half2*)(g_qh + ob + d0);
    __half2* kp = (__half2*)(g_kh + ob + d0);
    __half2* vp = (__half2*)(g_vh + ob + d0);

    float qa[4], qb[4], ka[4], kb[4];
#pragma unroll
    for (int i = 0; i < 4; i++) {
        qa[i] = (q1[i] * cc[i] - q2[i] * ss[i]) * sc;
        qb[i] = (q2[i] * cc[i] + q1[i] * ss[i]) * sc;
        ka[i] = k1[i] * cc[i] - k2[i] * ss[i];
        kb[i] = k2[i] * cc[i] + k1[i] * ss[i];
    }
    qp[0]  = __floats2half2_rn(qa[0], qa[1]);
    qp[1]  = __floats2half2_rn(qa[2], qa[3]);
    qp[16] = __floats2half2_rn(qb[0], qb[1]);
    qp[17] = __floats2half2_rn(qb[2], qb[3]);
    kp[0]  = __floats2half2_rn(ka[0], ka[1]);
    kp[1]  = __floats2half2_rn(ka[2], ka[3]);
    kp[16] = __floats2half2_rn(kb[0], kb[1]);
    kp[17] = __floats2half2_rn(kb[2], kb[3]);
    vp[0]  = v1a; vp[1]  = v1b;
    vp[16] = v2a; vp[17] = v2b;
}

// ---------------------------------------------------------------------------
// Flash attention: 128 q rows/CTA, 256 threads, 64-key tiles double-buffered.
// exp2-domain softmax (fp32 ex2); l via ALL-ONES-B MMA (layout-proof):
// B = all-ones 16x8 => every accumulator column = row sum of P.
// ---------------------------------------------------------------------------
#define SROW 72
#define TILE_B 9216u
#define FLASH_SMEM (6u * TILE_B)
#define ONES2 0x3C003C00u

__global__ __launch_bounds__(256, 2) void flash_mma()
{
    extern __shared__ char fsm[];
    const uint32_t sb = smem_u32(fsm);

    const int bh = blockIdx.y;
    const int qt = (gridDim.x - 1) - blockIdx.x;
    const int q0 = qt * 128;
    const int tid = threadIdx.x, wid = tid >> 5, lane = tid & 31;

    const size_t hb = (size_t)bh * Tt * Dd;
    const __half* Q = g_qh + hb + (size_t)q0 * Dd;
    const __half* Kp = g_kh + hb;
    const __half* Vp = g_vh + hb;

    auto soff = [&](int buf, int mat) -> uint32_t {
        return sb + (uint32_t)(buf * 2 + mat) * TILE_B;
    };
    const uint32_t soffQ = sb + 4 * TILE_B;

    {
#pragma unroll
        for (int i = 0; i < 4; i++) {
            int lin = tid + i * 256;
            int r = lin >> 3, c = (lin & 7) * 8;
            uint32_t so = (uint32_t)(r * SROW + c) * 2;
            cp16(soffQ + so, Q + (size_t)r * Dd + c);
        }
        CP_COMMIT();
#pragma unroll
        for (int i = 0; i < 2; i++) {
            int lin = tid + i * 256;
            int r = lin >> 3, c = (lin & 7) * 8;
            uint32_t so = (uint32_t)(r * SROW + c) * 2;
            cp16(soff(0, 0) + so, Kp + (size_t)r * Dd + c);
            cp16(soff(0, 1) + so, Vp + (size_t)r * Dd + c);
        }
        CP_COMMIT();
        CP_WAIT0();
        __syncthreads();
    }

    uint32_t QF[4][4];
    {
        const int row = wid * 16 + (lane & 15);
        const int ck  = (lane >> 4) * 8;
#pragma unroll
        for (int kk = 0; kk < 4; kk++) {
            uint32_t ao = (uint32_t)(row * SROW + kk * 16 + ck) * 2;
            ldmx4(QF[kk][0], QF[kk][1], QF[kk][2], QF[kk][3], soffQ + ao);
        }
    }

    float O[8][4];
#pragma unroll
    for (int i = 0; i < 8; i++)
#pragma unroll
        for (int e = 0; e < 4; e++) O[i][e] = 0.f;
    float Lacc[4] = {0.f, 0.f, 0.f, 0.f};
    float m0 = -1e30f, m1 = -1e30f;

    const int klrow = lane & 15;
    const int klk   = (lane >> 4) * 8;
    const int vg    = lane >> 3;
    const int vrow_in = (vg & 1) * 8 + (lane & 7);
    const int vcol_of = (vg >> 1) * 8;

    const int njt = 2 * qt + 2;
    for (int jt = 0; jt < njt; jt++) {
        const int buf = jt & 1;
        __syncthreads();
        if (jt + 1 < njt) {
            const int j1 = (jt + 1) * 64;
#pragma unroll
            for (int i = 0; i < 2; i++) {
                int lin = tid + i * 256;
                int r = lin >> 3, c = (lin & 7) * 8;
                uint32_t so = (uint32_t)(r * SROW + c) * 2;
                size_t gi = (size_t)(j1 + r) * Dd + c;
                cp16(soff(buf ^ 1, 0) + so, Kp + gi);
                cp16(soff(buf ^ 1, 1) + so, Vp + gi);
            }
            CP_COMMIT();
            CP_WAIT1();
        } else {
            CP_WAIT0();
        }
        __syncthreads();

        float S[8][4];
#pragma unroll
        for (int i = 0; i < 8; i++)
#pragma unroll
            for (int e = 0; e < 4; e++) S[i][e] = 0.f;

#pragma unroll
        for (int jg = 0; jg < 4; jg++) {
#pragma unroll
            for (int kk = 0; kk < 4; kk++) {
                uint32_t ao = (uint32_t)((jg * 16 + klrow) * SROW + kk * 16 + klk) * 2;
                uint32_t k0, k1, k2, k3;
                ldmx4(k0, k1, k2, k3, soff(buf, 0) + ao);
                mmaf16(S[jg * 2 + 0], QF[kk], k0, k2);
                mmaf16(S[jg * 2 + 1], QF[kk], k1, k3);
            }
        }

        if (jt >= 2 * qt) {
            const int off = q0 - jt * 64;
            const int r0l = wid * 16 + (lane >> 2);
            const int cb  = (lane & 3) * 2;
#pragma unroll
            for (int nf = 0; nf < 8; nf++) {
                int c0 = nf * 8 + cb;
                if (c0     > r0l + off)     S[nf][0] = -1e30f;
                if (c0 + 1 > r0l + off)     S[nf][1] = -1e30f;
                if (c0     > r0l + 8 + off) S[nf][2] = -1e30f;
                if (c0 + 1 > r0l + 8 + off) S[nf][3] = -1e30f;
            }
        }

        float tm0 = -1e30f, tm1 = -1e30f;
#pragma unroll
        for (int nf = 0; nf < 8; nf++) {
            tm0 = fmaxf(tm0, fmaxf(S[nf][0], S[nf][1]));
            tm1 = fmaxf(tm1, fmaxf(S[nf][2], S[nf][3]));
        }
        tm0 = fmaxf(tm0, __shfl_xor_sync(0xffffffff, tm0, 1));
        tm0 = fmaxf(tm0, __shfl_xor_sync(0xffffffff, tm0, 2));
        tm1 = fmaxf(tm1, __shfl_xor_sync(0xffffffff, tm1, 1));
        tm1 = fmaxf(tm1, __shfl_xor_sync(0xffffffff, tm1, 2));

        const bool grew = (tm0 > m0) || (tm1 > m1);
        if (__any_sync(0xffffffff, grew)) {
            float m0n = fmaxf(m0, tm0), m1n = fmaxf(m1, tm1);
            float sc0 = ex2(m0 - m0n), sc1 = ex2(m1 - m1n);
            Lacc[0] *= sc0; Lacc[1] *= sc0;
            Lacc[2] *= sc1; Lacc[3] *= sc1;
#pragma unroll
            for (int i = 0; i < 8; i++) {
                O[i][0] *= sc0; O[i][1] *= sc0;
                O[i][2] *= sc1; O[i][3] *= sc1;
            }
            m0 = m0n; m1 = m1n;
        }
#pragma unroll
        for (int nf = 0; nf < 8; nf++) {
            S[nf][0] = ex2(S[nf][0] - m0);
            S[nf][1] = ex2(S[nf][1] - m0);
            S[nf][2] = ex2(S[nf][2] - m1);
            S[nf][3] = ex2(S[nf][3] - m1);
        }

#pragma unroll
        for (int kk = 0; kk < 4; kk++) {
            const float* s0 = S[2 * kk];
            const float* s1 = S[2 * kk + 1];
            uint32_t P[4];
            P[0] = packf16(s0[0], s0[1]);
            P[1] = packf16(s0[2], s0[3]);
            P[2] = packf16(s1[0], s1[1]);
            P[3] = packf16(s1[2], s1[3]);
            mmaf16(Lacc, P, ONES2, ONES2);   // all-ones B: every col = row sum
#pragma unroll
            for (int dc = 0; dc < 4; dc++) {
                uint32_t vo = (uint32_t)((kk * 16 + vrow_in) * SROW + dc * 16 + vcol_of) * 2;
                uint32_t v0, v1, v2, v3;
                ldmx4t(v0, v1, v2, v3, soff(buf, 1) + vo);
                mmaf16(O[dc * 2 + 0], P, v0, v1);
                mmaf16(O[dc * 2 + 1], P, v2, v3);
            }
        }
    }

    const float i0 = 1.f / Lacc[0];   // row r sum (any column works)
    const float i1 = 1.f / Lacc[2];   // row r+8 sum

    const int b = bh >> 4, h = bh & 15;
    const int t0 = q0 + wid * 16 + (lane >> 2);
    const int t1 = t0 + 8;
    const size_t co = (size_t)h * Dd + (lane & 3) * 2;
    __half2* a0 = (__half2*)(g_ah + (size_t)(b * Tt + t0) * Cc + co);
    __half2* a1 = (__half2*)(g_ah + (size_t)(b * Tt + t1) * Cc + co);
#pragma unroll
    for (int nf = 0; nf < 8; nf++) {
        a0[nf * 4] = __floats2half2_rn(O[nf][0] * i0, O[nf][1] * i0);
        a1[nf * 4] = __floats2half2_rn(O[nf][2] * i1, O[nf][3] * i1);
    }
}

// ---------------------------------------------------------------------------
extern "C" void kernel_launch(void* const* d_in, const int* in_sizes, int n_in,
                              void* d_out, int out_size)
{
    const float* x      = (const float*)d_in[0];
    const float* w_attn = (const float*)d_in[1];
    const float* b_attn = (const float*)d_in[2];
    const float* w_proj = (const float*)d_in[3];
    const float* b_proj = (const float*)d_in[4];
    const float* cosp   = (const float*)d_in[5];
    const float* sinp   = (const float*)d_in[6];
    float* out = (float*)d_out;

    void *p_xh, *p_wh, *p_ph, *p_ah, *p_qkv;
    cudaGetSymbolAddress(&p_xh, g_xh);
    cudaGetSymbolAddress(&p_wh, g_wh);
    cudaGetSymbolAddress(&p_ph, g_ph);
    cudaGetSymbolAddress(&p_ah, g_ah);
    cudaGetSymbolAddress(&p_qkv, g_qkv);

    static bool once = false;
    if (!once) {
        cudaFuncSetAttribute(flash_mma,
                             cudaFuncAttributeMaxDynamicSharedMemorySize, FLASH_SMEM);
        cudaFuncSetAttribute(gemm_f16<0>,
                             cudaFuncAttributeMaxDynamicSharedMemorySize, GEMM_SMEM);
        cudaFuncSetAttribute(gemm_f16<1>,
                             cudaFuncAttributeMaxDynamicSharedMemorySize, GEMM_SMEM);
        cudaFuncSetAttribute(gemm_f16<0>,
                             cudaFuncAttributePreferredSharedMemoryCarveout, 100);
        cudaFuncSetAttribute(gemm_f16<1>,
                             cudaFuncAttributePreferredSharedMemoryCarveout, 100);
        once = true;
    }

    // 1) fused fp16 conversions
    {
        int total = N4_X + N4_W + N4_P;
        cvt_all<<<(total + 255) / 256, 256>>>(
            (const float4*)x, (const float4*)w_attn, (const float4*)w_proj,
            (__half2*)p_xh, (__half2*)p_wh, (__half2*)p_ph);
    }

    // 2) QKV projection -> g_qkv fp16
    {
        dim3 grid((3 * Cc) / 128, Mtot / 128);
        gemm_f16<1><<<grid, 256, GEMM_SMEM>>>(
            (const __half*)p_xh, (const __half*)p_wh,
            b_attn, p_qkv, 3 * Cc, Cc);
    }

    // 3) fused RoPE + relayout
    {
        int total = Bb * Tt * NHh * 8;
        rope_f16<<<total / 256, 256>>>(cosp, sinp);
    }

    // 4) flash attention -> g_ah fp16
    {
        dim3 grid(Tt / 128, Bb * NHh);
        flash_mma<<<grid, 256, FLASH_SMEM>>>();
    }

    // 5) output projection -> out fp32
    {
        dim3 grid(Cc / 128, Mtot / 128);
        gemm_f16<0><<<grid, 256, GEMM_SMEM>>>(
            (const __half*)p_ah, (const __half*)p_ph,
            b_proj, out, Cc, Cc);
    }
}

// round 17
// speedup vs baseline: 1.0222x; 1.0191x over previous
#include <cuda_runtime.h>
#include <cuda_fp16.h>
#include <cstdint>

#define Bb 4
#define Tt 2048
#define Cc 1024
#define NHh 16
#define Dd 64
#define Mtot (Bb * Tt)   // 8192

// ------------------------- scratch (__device__ globals) --------------------
__device__ __half g_qkv[(size_t)Bb * Tt * 3 * Cc];   // [B,T,3C] fp16
__device__ __half g_xh[(size_t)Mtot * Cc];
__device__ __half g_wh[(size_t)3 * Cc * Cc];
__device__ __half g_ph[(size_t)Cc * Cc];
__device__ __half g_ah[(size_t)Mtot * Cc];
// head-major [b*16+h][t][d] fp16 for attention
__device__ __half g_qh[(size_t)Mtot * Cc];
__device__ __half g_kh[(size_t)Mtot * Cc];
__device__ __half g_vh[(size_t)Mtot * Cc];

// ------------------------- helpers -----------------------------------------
__device__ __forceinline__ uint32_t smem_u32(const void* p) {
    uint32_t a;
    asm("{ .reg .u64 t; cvta.to.shared.u64 t, %1; cvt.u32.u64 %0, t; }"
        : "=r"(a) : "l"(p));
    return a;
}

__device__ __forceinline__ void ldmx4(uint32_t& r0, uint32_t& r1,
                                      uint32_t& r2, uint32_t& r3, uint32_t addr) {
    asm volatile("ldmatrix.sync.aligned.m8n8.x4.shared.b16 {%0,%1,%2,%3}, [%4];"
                 : "=r"(r0), "=r"(r1), "=r"(r2), "=r"(r3) : "r"(addr));
}

__device__ __forceinline__ void ldmx4t(uint32_t& r0, uint32_t& r1,
                                       uint32_t& r2, uint32_t& r3, uint32_t addr) {
    asm volatile("ldmatrix.sync.aligned.m8n8.x4.trans.shared.b16 {%0,%1,%2,%3}, [%4];"
                 : "=r"(r0), "=r"(r1), "=r"(r2), "=r"(r3) : "r"(addr));
}

__device__ __forceinline__ void mmaf16(float* d, const uint32_t* a,
                                       uint32_t b0, uint32_t b1) {
    asm volatile(
        "mma.sync.aligned.m16n8k16.row.col.f32.f16.f16.f32 "
        "{%0,%1,%2,%3}, {%4,%5,%6,%7}, {%8,%9}, {%0,%1,%2,%3};"
        : "+f"(d[0]), "+f"(d[1]), "+f"(d[2]), "+f"(d[3])
        : "r"(a[0]), "r"(a[1]), "r"(a[2]), "r"(a[3]), "r"(b0), "r"(b1));
}

__device__ __forceinline__ uint32_t packf16(float lo, float hi) {
    uint32_t r;
    asm("cvt.rn.f16x2.f32 %0, %1, %2;" : "=r"(r) : "f"(hi), "f"(lo));
    return r;
}

__device__ __forceinline__ float ex2(float x) {
    float r;
    asm("ex2.approx.ftz.f32 %0, %1;" : "=f"(r) : "f"(x));
    return r;
}

__device__ __forceinline__ void cp16(uint32_t dst, const void* src) {
    asm volatile("cp.async.cg.shared.global [%0], [%1], 16;" :: "r"(dst), "l"(src));
}
#define CP_COMMIT() asm volatile("cp.async.commit_group;" ::: "memory")
#define CP_WAIT0()  asm volatile("cp.async.wait_group 0;" ::: "memory")
#define CP_WAIT1()  asm volatile("cp.async.wait_group 1;" ::: "memory")

// ---------------------------------------------------------------------------
// fp16 single-pass GEMM, cp.async 3-stage ring (ONE sync/iter), BK=64.
// 256 threads, 8 warps (2m x 4n), warp tile 64x32, CTA tile 128x128.
// smem: 3 stages x 2 matrices x 128 x 144 B = 110592 B; 2 CTAs/SM.
// ---------------------------------------------------------------------------
#define SPAD 72
#define GMAT (128 * SPAD * 2u)

template <int OUTF16>
__global__ __launch_bounds__(256, 2)
void gemm_f16(const __half* __restrict__ A,
              const __half* __restrict__ B,
              const float* __restrict__ bias,
              void* __restrict__ CoutV, int N, int K)
{
    extern __shared__ char gsm[];
    const uint32_t sb = smem_u32(gsm);

    const int tid  = threadIdx.x;
    const int wid  = tid >> 5;
    const int lane = tid & 31;
    const int mw   = wid >> 2;
    const int nw   = wid & 3;
    const int m0   = blockIdx.y * 128;
    const int n0   = blockIdx.x * 128;

    auto stoff = [&](int s, int m) -> uint32_t {
        return sb + (uint32_t)(s * 2 + m) * GMAT;
    };

    const int kq = K >> 3;
    const int nk = K >> 6;
    const int rl = tid >> 3, cl = tid & 7;

    auto load_stage = [&](int s, int kc) {
#pragma unroll
        for (int i = 0; i < 4; i++) {
            const int r = rl + i * 32;
            const uint32_t so = (uint32_t)(r * (SPAD * 2) + cl * 16);
            cp16(stoff(s, 0) + so, (const uint4*)A + (size_t)(m0 + r) * kq + kc * 8 + cl);
            cp16(stoff(s, 1) + so, (const uint4*)B + (size_t)(n0 + r) * kq + kc * 8 + cl);
        }
    };

    const int lrow = lane & 15;
    const int lk   = (lane >> 4) * 8;
    uint32_t aoff[4], boff[2];
#pragma unroll
    for (int mt = 0; mt < 4; mt++)
        aoff[mt] = (uint32_t)(((mw * 64 + mt * 16 + lrow) * SPAD + lk) * 2);
#pragma unroll
    for (int ng = 0; ng < 2; ng++)
        boff[ng] = (uint32_t)(((nw * 32 + ng * 16 + lrow) * SPAD + lk) * 2);

    float acc[4][4][4];
#pragma unroll
    for (int i = 0; i < 4; i++)
#pragma unroll
        for (int j = 0; j < 4; j++)
#pragma unroll
            for (int e = 0; e < 4; e++) acc[i][j][e] = 0.f;

    load_stage(0, 0);
    CP_COMMIT();
    load_stage(1, 1);
    CP_COMMIT();

    int st = 0;
    for (int kc = 0; kc < nk; kc++) {
        CP_WAIT1();          // stage kc ready (kc+1 may be in flight)
        __syncthreads();     // data visible + WAR for buffer (kc+2)%3
        if (kc + 2 < nk) load_stage((st + 2) % 3, kc + 2);
        CP_COMMIT();

        const uint32_t uA = stoff(st, 0), uB = stoff(st, 1);
#pragma unroll
        for (int ks = 0; ks < 4; ks++) {
            const uint32_t kb = ks * 32;
            uint32_t ah[4][4];
#pragma unroll
            for (int mt = 0; mt < 4; mt++)
                ldmx4(ah[mt][0], ah[mt][1], ah[mt][2], ah[mt][3], uA + aoff[mt] + kb);
            uint32_t bh[2][4];
#pragma unroll
            for (int ng = 0; ng < 2; ng++)
                ldmx4(bh[ng][0], bh[ng][1], bh[ng][2], bh[ng][3], uB + boff[ng] + kb);
#pragma unroll
            for (int mt = 0; mt < 4; mt++)
#pragma unroll
                for (int ng = 0; ng < 2; ng++)
#pragma unroll
                    for (int sub = 0; sub < 2; sub++)
                        mmaf16(acc[mt][ng * 2 + sub], ah[mt],
                               bh[ng][sub], bh[ng][sub + 2]);
        }
        st = (st + 1) % 3;
    }

    const int erow = lane >> 2;
    const int ecol = (lane & 3) * 2;
#pragma unroll
    for (int mt = 0; mt < 4; mt++) {
#pragma unroll
        for (int nt = 0; nt < 4; nt++) {
            const int row = m0 + mw * 64 + mt * 16 + erow;
            const int col = n0 + nw * 32 + nt * 8 + ecol;
            const float b0 = bias[col], b1 = bias[col + 1];
            if (OUTF16) {
                __half* C = (__half*)CoutV;
                *(__half2*)(C + (size_t)row * N + col) =
                    __floats2half2_rn(acc[mt][nt][0] + b0, acc[mt][nt][1] + b1);
                *(__half2*)(C + (size_t)(row + 8) * N + col) =
                    __floats2half2_rn(acc[mt][nt][2] + b0, acc[mt][nt][3] + b1);
            } else {
                float* C = (float*)CoutV;
                float2 v;
                v.x = acc[mt][nt][0] + b0;
                v.y = acc[mt][nt][1] + b1;
                *(float2*)(C + (size_t)row * N + col) = v;
                v.x = acc[mt][nt][2] + b0;
                v.y = acc[mt][nt][3] + b1;
                *(float2*)(C + (size_t)(row + 8) * N + col) = v;
            }
        }
    }
}
#define GEMM_SMEM (3u * 2u * GMAT)   // 110592

// ---------------------------------------------------------------------------
// Fused fp32 -> fp16 conversion of x, w_attn, w_proj in ONE launch.
// ---------------------------------------------------------------------------
#define N4_X ((Mtot * Cc) / 4)
#define N4_W ((3 * Cc * Cc) / 4)
#define N4_P ((Cc * Cc) / 4)

__global__ void cvt_all(const float4* __restrict__ x,
                        const float4* __restrict__ w,
                        const float4* __restrict__ p,
                        __half2* __restrict__ xo,
                        __half2* __restrict__ wo,
                        __half2* __restrict__ po)
{
    int i = blockIdx.x * 256 + threadIdx.x;
    const float4* src;
    __half2* dst;
    if (i < N4_X) {
        src = x + i; dst = xo + 2 * i;
    } else if (i < N4_X + N4_W) {
        int j = i - N4_X;
        src = w + j; dst = wo + 2 * j;
    } else if (i < N4_X + N4_W + N4_P) {
        int j = i - N4_X - N4_W;
        src = p + j; dst = po + 2 * j;
    } else return;
    float4 v = *src;
    dst[0] = __floats2half2_rn(v.x, v.y);
    dst[1] = __floats2half2_rn(v.z, v.w);
}

// ---------------------------------------------------------------------------
// Fused RoPE + head-major relayout (fp16 in/out).
// ---------------------------------------------------------------------------
__global__ void rope_f16(const float* __restrict__ cosp,
                         const float* __restrict__ sinp)
{
    int idx = blockIdx.x * 256 + threadIdx.x;
    int ds = idx & 7;
    int h  = (idx >> 3) & 15;
    int t  = (idx >> 7) & 2047;
    int b  = idx >> 18;
    int d0 = ds * 4;

    const __half* base = g_qkv + ((size_t)(b * Tt + t)) * (3 * Cc) + h * Dd;
    auto ld4 = [&](const __half* p, float* o) {
        __half2 u0 = *(const __half2*)p;
        __half2 u1 = *(const __half2*)(p + 2);
        float2 f0 = __half22float2(u0), f1 = __half22float2(u1);
        o[0] = f0.x; o[1] = f0.y; o[2] = f1.x; o[3] = f1.y;
    };
    float q1[4], q2[4], k1[4], k2[4];
    ld4(base + d0, q1);           ld4(base + d0 + 32, q2);
    ld4(base + Cc + d0, k1);      ld4(base + Cc + d0 + 32, k2);
    __half2 v1a = *(const __half2*)(base + 2 * Cc + d0);
    __half2 v1b = *(const __half2*)(base + 2 * Cc + d0 + 2);
    __half2 v2a = *(const __half2*)(base + 2 * Cc + d0 + 32);
    __half2 v2b = *(const __half2*)(base + 2 * Cc + d0 + 34);

    float4 cw = *(const float4*)(cosp + t * Dd + d0);
    float4 sw = *(const float4*)(sinp + t * Dd + d0);
    float cc[4] = {cw.x, cw.y, cw.z, cw.w};
    float ss[4] = {sw.x, sw.y, sw.z, sw.w};

    const float sc = 0.125f * 1.44269504f;
    size_t ob = (((size_t)(b * NHh + h)) * Tt + t) * Dd;
    __half2* qp = (__half2*)(g_qh + ob + d0);
    __half2* kp = (__half2*)(g_kh + ob + d0);
    __half2* vp = (__half2*)(g_vh + ob + d0);

    float qa[4], qb[4], ka[4], kb[4];
#pragma unroll
    for (int i = 0; i < 4; i++) {
        qa[i] = (q1[i] * cc[i] - q2[i] * ss[i]) * sc;
        qb[i] = (q2[i] * cc[i] + q1[i] * ss[i]) * sc;
        ka[i] = k1[i] * cc[i] - k2[i] * ss[i];
        kb[i] = k2[i] * cc[i] + k1[i] * ss[i];
    }
    qp[0]  = __floats2half2_rn(qa[0], qa[1]);
    qp[1]  = __floats2half2_rn(qa[2], qa[3]);
    qp[16] = __floats2half2_rn(qb[0], qb[1]);
    qp[17] = __floats2half2_rn(qb[2], qb[3]);
    kp[0]  = __floats2half2_rn(ka[0], ka[1]);
    kp[1]  = __floats2half2_rn(ka[2], ka[3]);
    kp[16] = __floats2half2_rn(kb[0], kb[1]);
    kp[17] = __floats2half2_rn(kb[2], kb[3]);
    vp[0]  = v1a; vp[1]  = v1b;
    vp[16] = v2a; vp[17] = v2b;
}

// ---------------------------------------------------------------------------
// Flash attention: 128 q rows/CTA, 256 threads, 64-key tiles,
// 3-buffer ring (ONE sync/iter), exp2 softmax, l via all-ones-B MMA.
// smem: 3 bufs x {K,V} + Q(2 tiles) = 8 x 9216 = 73728 B; 2 CTAs/SM.
// ---------------------------------------------------------------------------
#define SROW 72
#define TILE_B 9216u
#define FLASH_SMEM (8u * TILE_B)
#define ONES2 0x3C003C00u

__global__ __launch_bounds__(256, 2) void flash_mma()
{
    extern __shared__ char fsm[];
    const uint32_t sb = smem_u32(fsm);

    const int bh = blockIdx.y;
    const int qt = (gridDim.x - 1) - blockIdx.x;
    const int q0 = qt * 128;
    const int tid = threadIdx.x, wid = tid >> 5, lane = tid & 31;

    const size_t hb = (size_t)bh * Tt * Dd;
    const __half* Q = g_qh + hb + (size_t)q0 * Dd;
    const __half* Kp = g_kh + hb;
    const __half* Vp = g_vh + hb;

    auto soff = [&](int buf, int mat) -> uint32_t {
        return sb + (uint32_t)(buf * 2 + mat) * TILE_B;
    };
    const uint32_t soffQ = sb + 6 * TILE_B;

    auto load_tile = [&](int buf, int j0) {
#pragma unroll
        for (int i = 0; i < 2; i++) {
            int lin = tid + i * 256;
            int r = lin >> 3, c = (lin & 7) * 8;
            uint32_t so = (uint32_t)(r * SROW + c) * 2;
            size_t gi = (size_t)(j0 + r) * Dd + c;
            cp16(soff(buf, 0) + so, Kp + gi);
            cp16(soff(buf, 1) + so, Vp + gi);
        }
    };

    const int njt = 2 * qt + 2;

    // prologue: G0 = Q + tile0 ; G1 = tile1
    {
#pragma unroll
        for (int i = 0; i < 4; i++) {
            int lin = tid + i * 256;
            int r = lin >> 3, c = (lin & 7) * 8;
            uint32_t so = (uint32_t)(r * SROW + c) * 2;
            cp16(soffQ + so, Q + (size_t)r * Dd + c);
        }
        load_tile(0, 0);
        CP_COMMIT();
        load_tile(1, 64);
        CP_COMMIT();
    }

    // wait for G0 (Q + tile0); G1 may be in flight
    CP_WAIT1();
    __syncthreads();

    uint32_t QF[4][4];
    {
        const int row = wid * 16 + (lane & 15);
        const int ck  = (lane >> 4) * 8;
#pragma unroll
        for (int kk = 0; kk < 4; kk++) {
            uint32_t ao = (uint32_t)(row * SROW + kk * 16 + ck) * 2;
            ldmx4(QF[kk][0], QF[kk][1], QF[kk][2], QF[kk][3], soffQ + ao);
        }
    }

    float O[8][4];
#pragma unroll
    for (int i = 0; i < 8; i++)
#pragma unroll
        for (int e = 0; e < 4; e++) O[i][e] = 0.f;
    float Lacc[4] = {0.f, 0.f, 0.f, 0.f};
    float m0 = -1e30f, m1 = -1e30f;

    const int klrow = lane & 15;
    const int klk   = (lane >> 4) * 8;
    const int vg    = lane >> 3;
    const int vrow_in = (vg & 1) * 8 + (lane & 7);
    const int vcol_of = (vg >> 1) * 8;

    int buf = 0;
    for (int jt = 0; jt < njt; jt++) {
        CP_WAIT1();          // tile jt ready (jt+1 may be in flight)
        __syncthreads();     // visibility + WAR for buffer (jt+2)%3
        if (jt + 2 < njt) load_tile((buf + 2) % 3, (jt + 2) * 64);
        CP_COMMIT();

        float S[8][4];
#pragma unroll
        for (int i = 0; i < 8; i++)
#pragma unroll
            for (int e = 0; e < 4; e++) S[i][e] = 0.f;

#pragma unroll
        for (int jg = 0; jg < 4; jg++) {
#pragma unroll
            for (int kk = 0; kk < 4; kk++) {
                uint32_t ao = (uint32_t)((jg * 16 + klrow) * SROW + kk * 16 + klk) * 2;
                uint32_t k0, k1, k2, k3;
                ldmx4(k0, k1, k2, k3, soff(buf, 0) + ao);
                mmaf16(S[jg * 2 + 0], QF[kk], k0, k2);
                mmaf16(S[jg * 2 + 1], QF[kk], k1, k3);
            }
        }

        if (jt >= 2 * qt) {
            const int off = q0 - jt * 64;
            const int r0l = wid * 16 + (lane >> 2);
            const int cb  = (lane & 3) * 2;
#pragma unroll
            for (int nf = 0; nf < 8; nf++) {
                int c0 = nf * 8 + cb;
                if (c0     > r0l + off)     S[nf][0] = -1e30f;
                if (c0 + 1 > r0l + off)     S[nf][1] = -1e30f;
                if (c0     > r0l + 8 + off) S[nf][2] = -1e30f;
                if (c0 + 1 > r0l + 8 + off) S[nf][3] = -1e30f;
            }
        }

        float tm0 = -1e30f, tm1 = -1e30f;
#pragma unroll
        for (int nf = 0; nf < 8; nf++) {
            tm0 = fmaxf(tm0, fmaxf(S[nf][0], S[nf][1]));
            tm1 = fmaxf(tm1, fmaxf(S[nf][2], S[nf][3]));
        }
        tm0 = fmaxf(tm0, __shfl_xor_sync(0xffffffff, tm0, 1));
        tm0 = fmaxf(tm0, __shfl_xor_sync(0xffffffff, tm0, 2));
        tm1 = fmaxf(tm1, __shfl_xor_sync(0xffffffff, tm1, 1));
        tm1 = fmaxf(tm1, __shfl_xor_sync(0xffffffff, tm1, 2));

        const bool grew = (tm0 > m0) || (tm1 > m1);
        if (__any_sync(0xffffffff, grew)) {
            float m0n = fmaxf(m0, tm0), m1n = fmaxf(m1, tm1);
            float sc0 = ex2(m0 - m0n), sc1 = ex2(m1 - m1n);
            Lacc[0] *= sc0; Lacc[1] *= sc0;
            Lacc[2] *= sc1; Lacc[3] *= sc1;
#pragma unroll
            for (int i = 0; i < 8; i++) {
                O[i][0] *= sc0; O[i][1] *= sc0;
                O[i][2] *= sc1; O[i][3] *= sc1;
            }
            m0 = m0n; m1 = m1n;
        }
#pragma unroll
        for (int nf = 0; nf < 8; nf++) {
            S[nf][0] = ex2(S[nf][0] - m0);
            S[nf][1] = ex2(S[nf][1] - m0);
            S[nf][2] = ex2(S[nf][2] - m1);
            S[nf][3] = ex2(S[nf][3] - m1);
        }

#pragma unroll
        for (int kk = 0; kk < 4; kk++) {
            const float* s0 = S[2 * kk];
            const float* s1 = S[2 * kk + 1];
            uint32_t P[4];
            P[0] = packf16(s0[0], s0[1]);
            P[1] = packf16(s0[2], s0[3]);
            P[2] = packf16(s1[0], s1[1]);
            P[3] = packf16(s1[2], s1[3]);
            mmaf16(Lacc, P, ONES2, ONES2);
#pragma unroll
            for (int dc = 0; dc < 4; dc++) {
                uint32_t vo = (uint32_t)((kk * 16 + vrow_in) * SROW + dc * 16 + vcol_of) * 2;
                uint32_t v0, v1, v2, v3;
                ldmx4t(v0, v1, v2, v3, soff(buf, 1) + vo);
                mmaf16(O[dc * 2 + 0], P, v0, v1);
                mmaf16(O[dc * 2 + 1], P, v2, v3);
            }
        }
        buf = (buf + 1) % 3;
    }

    const float i0 = 1.f / Lacc[0];
    const float i1 = 1.f / Lacc[2];

    const int b = bh >> 4, h = bh & 15;
    const int t0 = q0 + wid * 16 + (lane >> 2);
    const int t1 = t0 + 8;
    const size_t co = (size_t)h * Dd + (lane & 3) * 2;
    __half2* a0 = (__half2*)(g_ah + (size_t)(b * Tt + t0) * Cc + co);
    __half2* a1 = (__half2*)(g_ah + (size_t)(b * Tt + t1) * Cc + co);
#pragma unroll
    for (int nf = 0; nf < 8; nf++) {
        a0[nf * 4] = __floats2half2_rn(O[nf][0] * i0, O[nf][1] * i0);
        a1[nf * 4] = __floats2half2_rn(O[nf][2] * i1, O[nf][3] * i1);
    }
}

// ---------------------------------------------------------------------------
extern "C" void kernel_launch(void* const* d_in, const int* in_sizes, int n_in,
                              void* d_out, int out_size)
{
    const float* x      = (const float*)d_in[0];
    const float* w_attn = (const float*)d_in[1];
    const float* b_attn = (const float*)d_in[2];
    const float* w_proj = (const float*)d_in[3];
    const float* b_proj = (const float*)d_in[4];
    const float* cosp   = (const float*)d_in[5];
    const float* sinp   = (const float*)d_in[6];
    float* out = (float*)d_out;

    void *p_xh, *p_wh, *p_ph, *p_ah, *p_qkv;
    cudaGetSymbolAddress(&p_xh, g_xh);
    cudaGetSymbolAddress(&p_wh, g_wh);
    cudaGetSymbolAddress(&p_ph, g_ph);
    cudaGetSymbolAddress(&p_ah, g_ah);
    cudaGetSymbolAddress(&p_qkv, g_qkv);

    static bool once = false;
    if (!once) {
        cudaFuncSetAttribute(flash_mma,
                             cudaFuncAttributeMaxDynamicSharedMemorySize, FLASH_SMEM);
        cudaFuncSetAttribute(gemm_f16<0>,
                             cudaFuncAttributeMaxDynamicSharedMemorySize, GEMM_SMEM);
        cudaFuncSetAttribute(gemm_f16<1>,
                             cudaFuncAttributeMaxDynamicSharedMemorySize, GEMM_SMEM);
        cudaFuncSetAttribute(gemm_f16<0>,
                             cudaFuncAttributePreferredSharedMemoryCarveout, 100);
        cudaFuncSetAttribute(gemm_f16<1>,
                             cudaFuncAttributePreferredSharedMemoryCarveout, 100);
        once = true;
    }

    // 1) fused fp16 conversions
    {
        int total = N4_X + N4_W + N4_P;
        cvt_all<<<(total + 255) / 256, 256>>>(
            (const float4*)x, (const float4*)w_attn, (const float4*)w_proj,
            (__half2*)p_xh, (__half2*)p_wh, (__half2*)p_ph);
    }

    // 2) QKV projection -> g_qkv fp16
    {
        dim3 grid((3 * Cc) / 128, Mtot / 128);
        gemm_f16<1><<<grid, 256, GEMM_SMEM>>>(
            (const __half*)p_xh, (const __half*)p_wh,
            b_attn, p_qkv, 3 * Cc, Cc);
    }

    // 3) fused RoPE + relayout
    {
        int total = Bb * Tt * NHh * 8;
        rope_f16<<<total / 256, 256>>>(cosp, sinp);
    }

    // 4) flash attention -> g_ah fp16
    {
        dim3 grid(Tt / 128, Bb * NHh);
        flash_mma<<<grid, 256, FLASH_SMEM>>>();
    }

    // 5) output projection -> out fp32
    {
        dim3 grid(Cc / 128, Mtot / 128);
        gemm_f16<0><<<grid, 256, GEMM_SMEM>>>(
            (const __half*)p_ah, (const __half*)p_ph,
            b_proj, out, Cc, Cc);
    }
}